// round 2
// baseline (speedup 1.0000x reference)
#include <cuda_runtime.h>
#include <cooperative_groups.h>

namespace cg = cooperative_groups;

#define VOCABN 1000
#define EMBN   128
#define HIDN   256
#define G4N    1024   // 4*HID
#define BN     64
#define TN     1024

#define CL     8      // CTAs per cluster
#define GB     4      // batch rows per cluster
#define NTH    256
#define WSTRIDE 65    // float4 stride per W row (64 + 1 pad -> no LDS bank conflicts)

// Precomputed per-vocab gate projections: proj[v][g] = emb[v] . W_ih[g] + b_ih[g] + b_hh[g]
__device__ float g_proj[VOCABN * G4N];

__device__ __forceinline__ float sigf(float x) {
    return __fdividef(1.0f, 1.0f + __expf(-x));
}
__device__ __forceinline__ float tanhf_(float x) {
    // 1 - 2/(exp(2x)+1); saturates correctly at +-1 for large |x|
    return 1.0f - __fdividef(2.0f, __expf(2.0f * x) + 1.0f);
}

// ---------------------------------------------------------------------------
// Kernel 1: vocab projection table. 250 blocks x 256 threads, 4 vocab/block.
// ---------------------------------------------------------------------------
__global__ void __launch_bounds__(256) proj_kernel(
    const float* __restrict__ emb, const float* __restrict__ W_ih,
    const float* __restrict__ b_ih, const float* __restrict__ b_hh)
{
    __shared__ float4 es4[4][EMBN / 4];
    const int v0 = blockIdx.x * 4;
    const int tid = threadIdx.x;
    for (int i = tid; i < 4 * EMBN; i += 256) {
        int v = i >> 7, e = i & 127;
        ((float*)es4)[v * EMBN + e] = emb[(v0 + v) * EMBN + e];
    }
    __syncthreads();

    const float4* W4 = (const float4*)W_ih;
#pragma unroll
    for (int rr = 0; rr < 4; rr++) {
        int g = tid + rr * 256;  // gate row 0..1023
        float a0 = 0.f, a1 = 0.f, a2 = 0.f, a3 = 0.f;
#pragma unroll
        for (int e4 = 0; e4 < EMBN / 4; e4++) {
            float4 w  = W4[g * (EMBN / 4) + e4];
            float4 x0 = es4[0][e4];
            float4 x1 = es4[1][e4];
            float4 x2 = es4[2][e4];
            float4 x3 = es4[3][e4];
            a0 += w.x * x0.x + w.y * x0.y + w.z * x0.z + w.w * x0.w;
            a1 += w.x * x1.x + w.y * x1.y + w.z * x1.z + w.w * x1.w;
            a2 += w.x * x2.x + w.y * x2.y + w.z * x2.z + w.w * x2.w;
            a3 += w.x * x3.x + w.y * x3.y + w.z * x3.z + w.w * x3.w;
        }
        float bias = b_ih[g] + b_hh[g];
        g_proj[(v0 + 0) * G4N + g] = a0 + bias;
        g_proj[(v0 + 1) * G4N + g] = a1 + bias;
        g_proj[(v0 + 2) * G4N + g] = a2 + bias;
        g_proj[(v0 + 3) * G4N + g] = a3 + bias;
    }
}

// ---------------------------------------------------------------------------
// Kernel 2: the recurrence. Cluster of 8 CTAs handles 4 batch rows.
// CTA rank r owns h indices [r*32, r*32+32) and holds the 128 matching
// W_hh gate rows (i/f/g/o for those h indices) in SMEM.
// h[k][batch(4)] is double-buffered in every CTA's SMEM; after each step
// each CTA pushes its 32 new h values (x4 batch) to all 8 CTAs via DSMEM.
// ---------------------------------------------------------------------------
__global__ void __launch_bounds__(NTH, 1) __cluster_dims__(CL, 1, 1)
lstm_kernel(const int* __restrict__ tokens, const int* __restrict__ lengths,
            const float* __restrict__ W_hh, float* __restrict__ out)
{
    extern __shared__ float4 smem[];
    float4* Wsm = smem;                       // [128][WSTRIDE]
    float4* hb  = Wsm + 128 * WSTRIDE;        // [2][256]  h[k] as float4 over batch
    float4* red = hb + 512;                   // [128] k-half reduction
    float4* gsm = red + 128;                  // [128] full gates

    cg::cluster_group cluster = cg::this_cluster();
    const int rank = blockIdx.x;              // 0..7 within cluster
    const int cid  = blockIdx.y;              // 0..15 cluster id
    const int tid  = threadIdx.x;
    const int lr   = tid & 127;               // local gate-row 0..127
    const int hf   = tid >> 7;                // k-half 0/1
    const int base = rank * 32;
    const int grow = (lr >> 5) * HIDN + base + (lr & 31);  // global W_hh row
    const int b0   = cid * GB;

    // Load this CTA's W_hh slice (128 rows x 256 floats), padded stride.
    const float4* W4 = (const float4*)W_hh;
    for (int i = tid; i < 128 * 64; i += NTH) {
        int r = i >> 6, c = i & 63;
        int gr = ((r >> 5) * HIDN) + base + (r & 31);
        Wsm[r * WSTRIDE + c] = W4[gr * 64 + c];
    }
    for (int i = tid; i < 256; i += NTH)
        hb[i] = make_float4(0.f, 0.f, 0.f, 0.f);   // h buffer 0 = h0 = 0
    __syncthreads();

    const int len0 = lengths[b0 + 0];
    const int len1 = lengths[b0 + 1];
    const int len2 = lengths[b0 + 2];
    const int len3 = lengths[b0 + 3];
    int steps = max(max(len0, len1), max(len2, len3));
    if (steps > TN) steps = TN;

    float4 xw_cur = make_float4(0.f, 0.f, 0.f, 0.f);
    float4 xw_next = xw_cur;
    if (hf == 0) {
        xw_cur.x = g_proj[tokens[(b0 + 0) * TN + 0] * G4N + grow];
        xw_cur.y = g_proj[tokens[(b0 + 1) * TN + 0] * G4N + grow];
        xw_cur.z = g_proj[tokens[(b0 + 2) * TN + 0] * G4N + grow];
        xw_cur.w = g_proj[tokens[(b0 + 3) * TN + 0] * G4N + grow];
    }
    float4 hreg = make_float4(0.f, 0.f, 0.f, 0.f);  // warp0: my 4-batch h slice
    float4 creg = make_float4(0.f, 0.f, 0.f, 0.f);

    cluster.sync();

    for (int t = 0; t < steps; t++) {
        // Prefetch next step's input projection (independent of h).
        if (hf == 0) {
            int tn = min(t + 1, TN - 1);
            xw_next.x = g_proj[tokens[(b0 + 0) * TN + tn] * G4N + grow];
            xw_next.y = g_proj[tokens[(b0 + 1) * TN + tn] * G4N + grow];
            xw_next.z = g_proj[tokens[(b0 + 2) * TN + tn] * G4N + grow];
            xw_next.w = g_proj[tokens[(b0 + 3) * TN + tn] * G4N + grow];
        }

        // Partial matvec: this thread's gate row, its k-half, 4 batches.
        const float4* hcur = hb + (t & 1) * 256 + hf * 128;
        const float4* wrow = Wsm + lr * WSTRIDE + hf * 32;
        float4 acc = make_float4(0.f, 0.f, 0.f, 0.f);
#pragma unroll 8
        for (int k4 = 0; k4 < 32; k4++) {
            float4 w  = wrow[k4];
            float4 h0 = hcur[k4 * 4 + 0];
            float4 h1 = hcur[k4 * 4 + 1];
            float4 h2 = hcur[k4 * 4 + 2];
            float4 h3 = hcur[k4 * 4 + 3];
            acc.x += w.x * h0.x + w.y * h1.x + w.z * h2.x + w.w * h3.x;
            acc.y += w.x * h0.y + w.y * h1.y + w.z * h2.y + w.w * h3.y;
            acc.z += w.x * h0.z + w.y * h1.z + w.z * h2.z + w.w * h3.z;
            acc.w += w.x * h0.w + w.y * h1.w + w.z * h2.w + w.w * h3.w;
        }

        if (hf == 1) red[lr] = acc;
        __syncthreads();
        if (hf == 0) {
            float4 r2 = red[lr];
            float4 gv;
            gv.x = acc.x + r2.x + xw_cur.x;
            gv.y = acc.y + r2.y + xw_cur.y;
            gv.z = acc.z + r2.z + xw_cur.z;
            gv.w = acc.w + r2.w + xw_cur.w;
            gsm[lr] = gv;
            xw_cur = xw_next;
        }
        __syncthreads();

        // Warp 0: cell update for my 32 h indices x 4 batches, then push h_new.
        if (tid < 32) {
            float4 ig = gsm[tid];
            float4 fg = gsm[32 + tid];
            float4 gg = gsm[64 + tid];
            float4 og = gsm[96 + tid];
            {
                float i_ = sigf(ig.x), f_ = sigf(fg.x), z_ = tanhf_(gg.x), o_ = sigf(og.x);
                float cn = f_ * creg.x + i_ * z_;
                float hn = o_ * tanhf_(cn);
                if (t < len0) { creg.x = cn; hreg.x = hn; }
            }
            {
                float i_ = sigf(ig.y), f_ = sigf(fg.y), z_ = tanhf_(gg.y), o_ = sigf(og.y);
                float cn = f_ * creg.y + i_ * z_;
                float hn = o_ * tanhf_(cn);
                if (t < len1) { creg.y = cn; hreg.y = hn; }
            }
            {
                float i_ = sigf(ig.z), f_ = sigf(fg.z), z_ = tanhf_(gg.z), o_ = sigf(og.z);
                float cn = f_ * creg.z + i_ * z_;
                float hn = o_ * tanhf_(cn);
                if (t < len2) { creg.z = cn; hreg.z = hn; }
            }
            {
                float i_ = sigf(ig.w), f_ = sigf(fg.w), z_ = tanhf_(gg.w), o_ = sigf(og.w);
                float cn = f_ * creg.w + i_ * z_;
                float hn = o_ * tanhf_(cn);
                if (t < len3) { creg.w = cn; hreg.w = hn; }
            }
            // Push my h slice (with freeze applied) to every CTA's next buffer.
            float4* dst = hb + (((t & 1) ^ 1) * 256 + base + tid);
#pragma unroll
            for (int r = 0; r < CL; r++) {
                float4* p = cluster.map_shared_rank(dst, r);
                *p = hreg;
            }
        }
        cluster.sync();  // release my writes, acquire peers' h_new
    }

    if (tid < 32) {
        int hidx = base + tid;
        out[(b0 + 0) * HIDN + hidx] = hreg.x;
        out[(b0 + 1) * HIDN + hidx] = hreg.y;
        out[(b0 + 2) * HIDN + hidx] = hreg.z;
        out[(b0 + 3) * HIDN + hidx] = hreg.w;
    }
}

// ---------------------------------------------------------------------------
extern "C" void kernel_launch(void* const* d_in, const int* in_sizes, int n_in,
                              void* d_out, int out_size)
{
    const int*   tokens  = (const int*)d_in[0];
    const int*   lengths = (const int*)d_in[1];
    const float* emb     = (const float*)d_in[2];
    const float* W_ih    = (const float*)d_in[3];
    const float* W_hh    = (const float*)d_in[4];
    const float* b_ih    = (const float*)d_in[5];
    const float* b_hh    = (const float*)d_in[6];
    float* out = (float*)d_out;

    proj_kernel<<<VOCABN / 4, 256>>>(emb, W_ih, b_ih, b_hh);

    const int smem_bytes = (128 * WSTRIDE + 2 * 256 + 128 + 128) * (int)sizeof(float4);
    cudaFuncSetAttribute(lstm_kernel,
                         cudaFuncAttributeMaxDynamicSharedMemorySize, smem_bytes);
    dim3 grid(CL, BN / GB);
    lstm_kernel<<<grid, NTH, smem_bytes>>>(tokens, lengths, W_hh, out);
}